// round 6
// baseline (speedup 1.0000x reference)
#include <cuda_runtime.h>
#include <cuda_bf16.h>
#include <stdint.h>
#include <math.h>

#define HEADS 12
#define HEAD_SIZE 64
#define HIDDEN 768
#define EPROJ 1536
#define SEQ 1024
#define NB 8
#define NEGV 1000000000000.0f

// fp8 staging buffers
__device__ __align__(128) uint8_t g_x8[NB * SEQ * HIDDEN];            // x, scale 1
__device__ __align__(128) uint8_t g_w8[EPROJ * HIDDEN];               // W^T * 64
__device__ __align__(128) uint8_t g_q8[NB * HEADS * SEQ * HEAD_SIZE]; // q * 8
__device__ __align__(128) uint8_t g_k8[NB * HEADS * SEQ * HEAD_SIZE]; // k * 8

#define SWZ(o) ((o) ^ (((o) >> 3) & 0x70))     // 128B rows
#define SWZ64(o) ((o) ^ (((o) >> 3) & 0x30))   // 64B rows

__device__ __forceinline__ uint32_t smem_u32(const void* p) {
    uint32_t a;
    asm("{ .reg .u64 t; cvta.to.shared.u64 t, %1; cvt.u32.u64 %0, t; }"
        : "=r"(a) : "l"(p));
    return a;
}

__device__ __forceinline__ void ldmx4(uint32_t* r, uint32_t addr) {
    asm volatile("ldmatrix.sync.aligned.m8n8.x4.shared.b16 {%0,%1,%2,%3}, [%4];"
                 : "=r"(r[0]), "=r"(r[1]), "=r"(r[2]), "=r"(r[3]) : "r"(addr));
}
__device__ __forceinline__ void ldmx2(uint32_t* r, uint32_t addr) {
    asm volatile("ldmatrix.sync.aligned.m8n8.x2.shared.b16 {%0,%1}, [%2];"
                 : "=r"(r[0]), "=r"(r[1]) : "r"(addr));
}
// fp8 e4m3 mma: m16n8k32, fp32 accum (sm_89+)
__device__ __forceinline__ void mma8(float* c, const uint32_t* a,
                                     const uint32_t* b) {
    asm volatile(
        "mma.sync.aligned.m16n8k32.row.col.f32.e4m3.e4m3.f32 "
        "{%0,%1,%2,%3}, {%4,%5,%6,%7}, {%8,%9}, {%0,%1,%2,%3};"
        : "+f"(c[0]), "+f"(c[1]), "+f"(c[2]), "+f"(c[3])
        : "r"(a[0]), "r"(a[1]), "r"(a[2]), "r"(a[3]), "r"(b[0]), "r"(b[1]));
}

// pack two floats -> e4m3x2 (lo = first arg)
__device__ __forceinline__ uint16_t pack2_e4m3(float lo, float hi) {
    uint16_t r;
    asm("cvt.rn.satfinite.e4m3x2.f32 %0, %1, %2;" : "=h"(r) : "f"(hi), "f"(lo));
    return r;
}
__device__ __forceinline__ uint32_t pack4_e4m3(float a0, float a1, float a2,
                                               float a3) {
    uint16_t lo = pack2_e4m3(a0, a1);
    uint16_t hi = pack2_e4m3(a2, a3);
    return (uint32_t)lo | ((uint32_t)hi << 16);
}

// ---------------------------------------------------------------------------
// conversion kernels
// ---------------------------------------------------------------------------
__global__ void conv_x_kernel(const float* __restrict__ x) {
    int i = blockIdx.x * blockDim.x + threadIdx.x;  // 8 floats per thread
    float4 v0 = ((const float4*)x)[i * 2];
    float4 v1 = ((const float4*)x)[i * 2 + 1];
    uint2 u;
    u.x = pack4_e4m3(v0.x, v0.y, v0.z, v0.w);
    u.y = pack4_e4m3(v1.x, v1.y, v1.z, v1.w);
    ((uint2*)g_x8)[i] = u;
}

__global__ void conv_wt_kernel(const float* __restrict__ W) {
    __shared__ float t[32][33];
    const int bx = blockIdx.x * 32, by = blockIdx.y * 32;  // bx: e cols, by: d rows
    const int tx = threadIdx.x, ty = threadIdx.y;
#pragma unroll
    for (int j = 0; j < 4; j++)
        t[ty + j * 8][tx] = W[(size_t)(by + ty + j * 8) * EPROJ + bx + tx];
    __syncthreads();
    const int r2 = ty + (tx >> 3) * 8;   // out-row (e) 0..31
    const int c4 = (tx & 7) * 4;         // out-col (d) group
    uint32_t p = pack4_e4m3(t[c4 + 0][r2] * 64.f, t[c4 + 1][r2] * 64.f,
                            t[c4 + 2][r2] * 64.f, t[c4 + 3][r2] * 64.f);
    *(uint32_t*)(g_w8 + (size_t)(bx + r2) * HIDDEN + by + c4) = p;
}

// ---------------------------------------------------------------------------
// Kernel 1: proj = x @ W (+bias), RoPE -> g_q8 / g_k8 (e4m3, scale 8)
// CTA tile 128x128, K in 6 chunks of 128 (fp8 bytes = 128B rows, SW128).
// 8 warps: 2(m) x 4(n), warp tile 64x32; mma m16n8k32 e4m3.
// ---------------------------------------------------------------------------
__global__ void proj_kernel(const float* __restrict__ bias) {
    __shared__ __align__(128) uint8_t sA[128 * 128];  // 16KB
    __shared__ __align__(128) uint8_t sB[128 * 128];  // 16KB
    __shared__ float s_inv[32];
    __shared__ float s_bias[128];

    const int tid = threadIdx.x;
    const int lane = tid & 31;
    const int wid = tid >> 5;
    const int wm = wid & 1;
    const int wn = wid >> 1;
    const int h = blockIdx.x;
    const int rowBase = blockIdx.y * 128;
    const int colBase = h * 128;

    if (tid < 32) s_inv[tid] = exp2f(-(float)(2 * tid) * (13.287712379549449f / 64.0f));
    if (tid < 128) s_bias[tid] = bias[colBase + tid];

    const uint32_t sAb = smem_u32(sA);
    const uint32_t sBb = smem_u32(sB);

    float acc[4][4][4] = {};

    for (int ch = 0; ch < 6; ch++) {
        const int k0 = ch * 128;
        __syncthreads();
#pragma unroll
        for (int i = 0; i < 4; i++) {
            int e = tid + i * 256;   // 1024 uint4 per tile
            int r = e >> 3;
            int c = e & 7;
            uint32_t so = SWZ((uint32_t)(r * 128 + c * 16));
            *(uint4*)(sA + so) =
                *(const uint4*)(g_x8 + (size_t)(rowBase + r) * HIDDEN + k0 + c * 16);
            *(uint4*)(sB + so) =
                *(const uint4*)(g_w8 + (size_t)(colBase + r) * HIDDEN + k0 + c * 16);
        }
        __syncthreads();

#pragma unroll
        for (int ks = 0; ks < 4; ks++) {   // 4 x K=32 per chunk
            uint32_t aF[4][4], bF[4][2];
#pragma unroll
            for (int mi = 0; mi < 4; mi++) {
                int r = wm * 64 + mi * 16 + (lane & 15);
                int cc = ks * 2 + (lane >> 4);
                ldmx4(aF[mi], sAb + SWZ((uint32_t)(r * 128 + cc * 16)));
            }
#pragma unroll
            for (int ni = 0; ni < 4; ni++) {
                int l = lane & 15;
                int r = wn * 32 + ni * 8 + (l & 7);
                int cc = ks * 2 + (l >> 3);
                ldmx2(bF[ni], sBb + SWZ((uint32_t)(r * 128 + cc * 16)));
            }
#pragma unroll
            for (int mi = 0; mi < 4; mi++)
#pragma unroll
                for (int ni = 0; ni < 4; ni++)
                    mma8(acc[mi][ni], aF[mi], bF[ni]);
        }
    }

    // Epilogue: unscale (1/64), +bias, RoPE, scale 8, pack e4m3x2.
    const int colW = wn * 32;
    const int half = colW >> 6;           // 0=q, 1=k
    uint8_t* dstBase = half ? g_k8 : g_q8;
#pragma unroll
    for (int mi = 0; mi < 4; mi++) {
#pragma unroll
        for (int rr = 0; rr < 2; rr++) {
            const int r = rowBase + wm * 64 + mi * 16 + (lane >> 2) + rr * 8;
            const int bb = r >> 10;
            const int n = r & (SEQ - 1);
            const float fn = (float)n;
            uint8_t* drow =
                dstBase + ((size_t)(bb * HEADS + h) * SEQ + n) * HEAD_SIZE;
#pragma unroll
            for (int ni = 0; ni < 4; ni++) {
                const int col = colW + ni * 8 + (lane & 3) * 2;
                const int d0 = col & 63;
                float s, cs;
                sincosf(fn * s_inv[d0 >> 1], &s, &cs);
                const float v0 = acc[mi][ni][rr * 2 + 0] * 0.015625f + s_bias[col];
                const float v1 = acc[mi][ni][rr * 2 + 1] * 0.015625f + s_bias[col + 1];
                const float o0 = (v0 * cs - v1 * s) * 8.0f;
                const float o1 = (v1 * cs + v0 * s) * 8.0f;
                *(uint16_t*)(drow + d0) = pack2_e4m3(o0, o1);
            }
        }
    }
}

// ---------------------------------------------------------------------------
// Kernel 2: logits tile 128x128 per CTA: D = q @ k^T (fp8, scale 64),
// unscale + mask/causal/scale, direct float2 stores (best measured epilogue).
// q/k tiles: 128 rows x 64B, SW64 swizzle (8KB each).
// ---------------------------------------------------------------------------
__global__ void logits_kernel(const float* __restrict__ mask,
                              float* __restrict__ out) {
    __shared__ __align__(128) uint8_t sQ[128 * 64];  // 8KB
    __shared__ __align__(128) uint8_t sK[128 * 64];  // 8KB
    __shared__ float s_mk[128];

    const int tid = threadIdx.x;
    const int lane = tid & 31;
    const int wid = tid >> 5;
    const int wm = wid & 1;
    const int wn = wid >> 1;
    const int z = blockIdx.z;
    const int b = z / HEADS;
    const int m0 = blockIdx.y << 7;
    const int n0 = blockIdx.x << 7;

    const uint8_t* qsrc = g_q8 + ((size_t)z * SEQ + m0) * HEAD_SIZE;
    const uint8_t* ksrc = g_k8 + ((size_t)z * SEQ + n0) * HEAD_SIZE;

#pragma unroll
    for (int i = 0; i < 2; i++) {
        int e = tid + i * 256;           // 512 uint4 per tile
        int r = e >> 2;
        int c = e & 3;
        uint32_t so = SWZ64((uint32_t)(r * 64 + c * 16));
        *(uint4*)(sQ + so) = ((const uint4*)qsrc)[e];
        *(uint4*)(sK + so) = ((const uint4*)ksrc)[e];
    }
    if (tid < 128) s_mk[tid] = mask[(size_t)b * SEQ + n0 + tid];
    __syncthreads();

    const uint32_t sQb = smem_u32(sQ);
    const uint32_t sKb = smem_u32(sK);

    float acc[4][4][4] = {};
#pragma unroll
    for (int ks = 0; ks < 2; ks++) {     // 2 x K=32
        uint32_t aF[4][4], bF[4][2];
#pragma unroll
        for (int mi = 0; mi < 4; mi++) {
            int r = wm * 64 + mi * 16 + (lane & 15);
            int cc = ks * 2 + (lane >> 4);
            ldmx4(aF[mi], sQb + SWZ64((uint32_t)(r * 64 + cc * 16)));
        }
#pragma unroll
        for (int ni = 0; ni < 4; ni++) {
            int l = lane & 15;
            int r = wn * 32 + ni * 8 + (l & 7);
            int cc = ks * 2 + (l >> 3);
            ldmx2(bF[ni], sKb + SWZ64((uint32_t)(r * 64 + cc * 16)));
        }
#pragma unroll
        for (int mi = 0; mi < 4; mi++)
#pragma unroll
            for (int ni = 0; ni < 4; ni++)
                mma8(acc[mi][ni], aF[mi], bF[ni]);
    }

    // Epilogue: unscale 1/64, mask, causal, scale; direct float2 stores.
#pragma unroll
    for (int mi = 0; mi < 4; mi++) {
#pragma unroll
        for (int rr = 0; rr < 2; rr++) {
            const int m = m0 + wm * 64 + mi * 16 + (lane >> 2) + rr * 8;
            const float mq = mask[(size_t)b * SEQ + m];
            const float rbias = NEGV * (mq - 1.0f);
            float* orow = out + ((size_t)z * SEQ + m) * SEQ;
#pragma unroll
            for (int ni = 0; ni < 4; ni++) {
                const int col = wn * 32 + ni * 8 + (lane & 3) * 2;
                const int nn = n0 + col;
                float2 o;
#pragma unroll
                for (int q = 0; q < 2; q++) {
                    const float mk = s_mk[col + q];
                    float v = acc[mi][ni][rr * 2 + q] * 0.015625f;
                    v = v * mq + rbias;
                    v = v * mk + NEGV * (mk - 1.0f);
                    if (m > nn + q) v -= NEGV;
                    (&o.x)[q] = v * 0.125f;
                }
                *(float2*)(orow + nn) = o;
            }
        }
    }
}

// ---------------------------------------------------------------------------
extern "C" void kernel_launch(void* const* d_in, const int* in_sizes, int n_in,
                              void* d_out, int out_size) {
    const float* x = (const float*)d_in[0];
    const float* W = (const float*)d_in[1];
    const float* bias = (const float*)d_in[2];
    const float* mask = (const float*)d_in[3];
    float* out = (float*)d_out;

    conv_x_kernel<<<(NB * SEQ * HIDDEN / 8) / 256, 256>>>(x);
    conv_wt_kernel<<<dim3(EPROJ / 32, HIDDEN / 32), dim3(32, 8)>>>(W);

    proj_kernel<<<dim3(EPROJ / 128, NB * SEQ / 128), 256>>>(bias);

    logits_kernel<<<dim3(SEQ / 128, SEQ / 128, NB * HEADS), 256>>>(mask, out);
}